// round 10
// baseline (speedup 1.0000x reference)
#include <cuda_runtime.h>

// Problem geometry (fixed by the reference)
#define WIDTH   1000
#define HEIGHT  1000
#define PS      5
#define NT      10
#define PPR     (WIDTH / PS)          // 200 patches per patch-row
#define NPIX    (WIDTH * HEIGHT)      // 1,000,000

constexpr int PATCHES_PER_BLOCK = 25;
constexpr int COLS_PER_BLOCK    = PATCHES_PER_BLOCK * PS;   // 125
constexpr int SEGS              = WIDTH / COLS_PER_BLOCK;   // 8
constexpr int THREADS           = 128;
constexpr int COEF_PER_PATCH    = 3 * NT * 2;               // 60 floats = 240 B
constexpr int CH_VEC16          = PATCHES_PER_BLOCK * 5;    // 125 x 16B per channel

using ull = unsigned long long;

// Packed dual-FMA on the f32x2 pipe (ptxas never auto-fuses this).
__device__ __forceinline__ ull fma2(ull a, ull b, ull c) {
    ull d;
    asm("fma.rn.f32x2 %0, %1, %2, %3;" : "=l"(d) : "l"(a), "l"(b), "l"(c));
    return d;
}
__device__ __forceinline__ void unpack2(ull h, float& lo, float& hi) {
    asm("mov.b64 {%0, %1}, %2;" : "=f"(lo), "=f"(hi) : "l"(h));
}
__device__ __forceinline__ void cp_async16(void* smem_dst, const void* gmem_src) {
    unsigned saddr = (unsigned)__cvta_generic_to_shared(smem_dst);
    asm volatile("cp.async.cg.shared.global [%0], [%1], 16;" :: "r"(saddr), "l"(gmem_src));
}

__global__ __launch_bounds__(THREADS, 11)   // <=46 regs -> 11 CTAs/SM -> ONE wave
void ts_approx_kernel(const float* __restrict__ pix,     // [NPIX, 2]
                      const float* __restrict__ coef,    // [NPATCH, 3, NT, 2]
                      const float* __restrict__ bias,    // [NPATCH, 3]
                      float* __restrict__ out)           // [3, NPIX]
{
    // Channel-major staging: s_coef[ch] holds 25 patches x 5 float4.
    __shared__ float4 s_coef[3][CH_VEC16];               // 6000 B

    const int b    = blockIdx.x;
    const int pr   = b / SEGS;                    // patch-row 0..199
    const int seg  = b % SEGS;                    // 0..7
    const int row0 = pr * PS;
    const int c    = threadIdx.x;                 // 0..124 active for compute
    const int patch0 = pr * PPR + seg * PATCHES_PER_BLOCK;
    const int n0   = row0 * WIDTH + seg * COLS_PER_BLOCK + c;

    // ── Pixel + bias loads first (register LDG, latency overlaps staging).
    const ull* __restrict__ pixq = reinterpret_cast<const ull*>(pix);
    ull xy[PS];
    float bg[3];
    if (c < COLS_PER_BLOCK) {
        #pragma unroll
        for (int r = 0; r < PS; r++)
            xy[r] = pixq[n0 + r * WIDTH];                 // default caching: L2-resident replays
        const int pat = patch0 + c / PS;
        #pragma unroll
        for (int ch = 0; ch < 3; ch++)
            bg[ch] = __ldg(&bias[pat * 3 + ch]);          // 5-lane L1 broadcast
    }

    // ── Coefficient staging in TWO groups: ch0 first (1/3 bytes), ch1+ch2 after.
    //    gmem layout per patch: [3][10][2] -> channel ch = 5 float4 at offset ch*5.
    const float4* gc = reinterpret_cast<const float4*>(coef) + (size_t)patch0 * 15;
    // group 0: channel 0 (125 x 16B)
    for (int i = threadIdx.x; i < CH_VEC16; i += THREADS) {
        const int p = i / 5, k = i % 5;
        cp_async16(&s_coef[0][i], &gc[p * 15 + 0 + k]);
    }
    asm volatile("cp.async.commit_group;" ::: "memory");
    // group 1: channels 1 and 2 (250 x 16B)
    for (int i = threadIdx.x; i < 2 * CH_VEC16; i += THREADS) {
        const int ch = 1 + i / CH_VEC16;
        const int j  = i % CH_VEC16;
        const int p = j / 5, k = j % 5;
        cp_async16(&s_coef[ch][j], &gc[p * 15 + ch * 5 + k]);
    }
    asm volatile("cp.async.commit_group;" ::: "memory");

    const int pl = c / PS;                        // local patch 0..24

    auto do_channel = [&](int ch) {
        // 5 x LDS.128; lane stride 80B within channel across ~7 patches -> conflict-free.
        const ulonglong2* cfc = reinterpret_cast<const ulonglong2*>(&s_coef[ch][pl * 5]);
        const ulonglong2 u0 = cfc[0];   // (c0, c1) pairs (a_t, b_t)
        const ulonglong2 u1 = cfc[1];
        const ulonglong2 u2 = cfc[2];
        const ulonglong2 u3 = cfc[3];
        const ulonglong2 u4 = cfc[4];
        const float bch = bg[ch];

        #pragma unroll
        for (int r = 0; r < PS; r++) {
            ull h = u4.y;                  // (a9, b9)
            h = fma2(h, xy[r], u4.x);
            h = fma2(h, xy[r], u3.y);
            h = fma2(h, xy[r], u3.x);
            h = fma2(h, xy[r], u2.y);
            h = fma2(h, xy[r], u2.x);
            h = fma2(h, xy[r], u1.y);
            h = fma2(h, xy[r], u1.x);
            h = fma2(h, xy[r], u0.y);
            h = fma2(h, xy[r], u0.x);      // + (a0, b0)
            float hx, hy;
            unpack2(h, hx, hy);
            __stcs(&out[(size_t)ch * NPIX + n0 + r * WIDTH], hx + (hy + bch));
        }
    };

    // ── Wait for ch0 only (group 1 still in flight), compute ch0, then the rest.
    asm volatile("cp.async.wait_group 1;" ::: "memory");
    __syncthreads();
    if (c < COLS_PER_BLOCK) do_channel(0);

    asm volatile("cp.async.wait_group 0;" ::: "memory");
    __syncthreads();
    if (c < COLS_PER_BLOCK) { do_channel(1); do_channel(2); }
}

extern "C" void kernel_launch(void* const* d_in, const int* in_sizes, int n_in,
                              void* d_out, int out_size)
{
    const float* pix  = (const float*)d_in[0];   // [1e6, 2]
    const float* coef = (const float*)d_in[1];   // [40000, 3, 10, 2]
    const float* bias = (const float*)d_in[2];   // [40000, 3]
    float* out        = (float*)d_out;           // [3, 1e6]

    const int nblocks = (HEIGHT / PS) * SEGS;    // 200 * 8 = 1600
    ts_approx_kernel<<<nblocks, THREADS>>>(pix, coef, bias, out);
}